// round 4
// baseline (speedup 1.0000x reference)
#include <cuda_runtime.h>
#include <cuda_bf16.h>

// KernelApply: out[b,c,h,w] = sum_{i,j} softmax(kern[b,:,h,w])[i*5+j] * data_pad[b,c,h+i-2,w+j-2]
// data: [B,C,H,W] f32; kernels: [B,25,H,W] f32; out: [B,C,H,W] f32

#define B_ 4
#define C_ 3
#define H_ 720
#define W_ 1280
#define K_ 5
#define R_ 2

__global__ __launch_bounds__(256, 5) void kpn_apply_v4(
    const float* __restrict__ data,
    const float* __restrict__ kern,
    float* __restrict__ out)
{
    const int HW = H_ * W_;
    const int GP = HW / 2;                        // 2-pixel groups per image
    int g = blockIdx.x * blockDim.x + threadIdx.x;
    if (g >= B_ * GP) return;

    int b   = g / GP;
    int pos = (g - b * GP) * 2;                   // first pixel (even)
    int h   = pos / W_;
    int w   = pos - h * W_;

    const float* kp = kern + (size_t)b * (K_ * K_) * HW + pos;  // tap t: kp[t*HW], kp[t*HW+1]
    const float* dp = data + (size_t)b * C_ * HW;
    float*       op = out  + (size_t)b * C_ * HW + pos;

    if (h >= R_ && h < H_ - R_ && w >= 2 && w <= W_ - 4) {
        // ---- interior: 2 pixels, row-by-row, float2 everywhere ----
        float s0 = 0.f, s1 = 0.f;
        float a[C_][2] = {};

        #pragma unroll
        for (int i = 0; i < K_; i++) {
            // batch this row's 5 kernel-tap vector loads + 9 data vector loads
            float2 kv[K_];
            #pragma unroll
            for (int j = 0; j < K_; j++)
                kv[j] = *(const float2*)(kp + (i * K_ + j) * HW);

            const float* drow = dp + (h + i - R_) * W_ + (w - R_);  // 8B-aligned
            float2 d[C_][3];                       // 6-float window per channel
            #pragma unroll
            for (int c = 0; c < C_; c++) {
                d[c][0] = *(const float2*)(drow + c * HW);
                d[c][1] = *(const float2*)(drow + c * HW + 2);
                d[c][2] = *(const float2*)(drow + c * HW + 4);
            }

            float e0[K_], e1[K_];
            #pragma unroll
            for (int j = 0; j < K_; j++) {
                e0[j] = __expf(kv[j].x);           // softmax w/o shift: inputs ~N(0,1)
                e1[j] = __expf(kv[j].y);
                s0 += e0[j];
                s1 += e1[j];
            }

            #pragma unroll
            for (int c = 0; c < C_; c++) {
                float w0 = d[c][0].x, w1 = d[c][0].y, w2 = d[c][1].x;
                float w3 = d[c][1].y, w4 = d[c][2].x, w5 = d[c][2].y;
                a[c][0] += e0[0] * w0 + e0[1] * w1 + e0[2] * w2 + e0[3] * w3 + e0[4] * w4;
                a[c][1] += e1[0] * w1 + e1[1] * w2 + e1[2] * w3 + e1[3] * w4 + e1[4] * w5;
            }
        }

        float i0 = __frcp_rn(s0), i1 = __frcp_rn(s1);
        #pragma unroll
        for (int c = 0; c < C_; c++) {
            float2 o;
            o.x = a[c][0] * i0;
            o.y = a[c][1] * i1;
            *(float2*)(op + c * HW) = o;
        }
    } else {
        // ---- border: scalar per pixel (zero-pad data, full softmax denominator) ----
        #pragma unroll
        for (int p = 0; p < 2; p++) {
            int wp = w + p;
            float sum = 0.f, a0 = 0.f, a1 = 0.f, a2 = 0.f;
            #pragma unroll
            for (int i = 0; i < K_; i++) {
                int yy = h + i - R_;
                bool yok = (yy >= 0) & (yy < H_);
                #pragma unroll
                for (int j = 0; j < K_; j++) {
                    int xx = wp + j - R_;
                    float e = __expf(kp[(i * K_ + j) * HW + p]);
                    sum += e;
                    if (yok & (xx >= 0) & (xx < W_)) {
                        const float* d0 = dp + yy * W_ + xx;
                        a0 += e * d0[0];
                        a1 += e * d0[HW];
                        a2 += e * d0[2 * HW];
                    }
                }
            }
            float inv = __frcp_rn(sum);
            op[p]          = a0 * inv;
            op[HW + p]     = a1 * inv;
            op[2 * HW + p] = a2 * inv;
        }
    }
}

extern "C" void kernel_launch(void* const* d_in, const int* in_sizes, int n_in,
                              void* d_out, int out_size)
{
    const float* data = (const float*)d_in[0];
    const float* kern = (const float*)d_in[1];
    float* out = (float*)d_out;

    const int groups  = B_ * H_ * W_ / 2;       // 2 pixels per thread
    const int threads = 256;
    const int blocks  = (groups + threads - 1) / threads;
    kpn_apply_v4<<<blocks, threads>>>(data, kern, out);
}

// round 5
// speedup vs baseline: 1.2374x; 1.2374x over previous
#include <cuda_runtime.h>
#include <cuda_bf16.h>
#include <cstdint>

// KernelApply: out[b,c,h,w] = sum_{i,j} softmax(kern[b,:,h,w])[i*5+j] * data_pad[b,c,h+i-2,w+j-2]
// data: [B,C,H,W] f32; kernels: [B,25,H,W] f32; out: [B,C,H,W] f32
//
// v5: kernels tensor (80% of DRAM traffic) staged per-block via cp.async.bulk
// (TMA) into smem -- in-flight bytes live in smem, not registers, so MLP no
// longer competes with occupancy.

#define B_ 4
#define C_ 3
#define H_ 720
#define W_ 1280
#define K_ 5
#define R_ 2
#define TPB 256

__global__ __launch_bounds__(TPB) void kpn_apply_v5(
    const float* __restrict__ data,
    const float* __restrict__ kern,
    float* __restrict__ out)
{
    __shared__ __align__(128) float sk[K_ * K_ * TPB];   // 25 taps x 256 px = 25.6 KB
    __shared__ __align__(8) uint64_t mbar;

    const int HW = H_ * W_;
    const int TILES = HW / TPB;                  // 3600 tiles per image
    int tile = blockIdx.x;
    int b    = tile / TILES;
    int pos0 = (tile - b * TILES) * TPB;         // first pixel of this tile (1KB-aligned)
    int tid  = threadIdx.x;

    const float* kbase = kern + (size_t)b * (K_ * K_) * HW + pos0;

    uint32_t mbar_a = (uint32_t)__cvta_generic_to_shared(&mbar);
    uint32_t sk_a   = (uint32_t)__cvta_generic_to_shared(sk);

    if (tid == 0) {
        asm volatile("mbarrier.init.shared.b64 [%0], 1;" :: "r"(mbar_a) : "memory");
    }
    __syncthreads();

    if (tid == 0) {
        asm volatile("mbarrier.arrive.expect_tx.shared.b64 _, [%0], %1;"
                     :: "r"(mbar_a), "r"(K_ * K_ * TPB * 4) : "memory");
        #pragma unroll
        for (int t = 0; t < K_ * K_; t++) {
            asm volatile(
                "cp.async.bulk.shared::cta.global.mbarrier::complete_tx::bytes "
                "[%0], [%1], %2, [%3];"
                :: "r"(sk_a + t * TPB * 4),
                   "l"(kbase + (size_t)t * HW),
                   "r"(TPB * 4),
                   "r"(mbar_a)
                : "memory");
        }
    }

    // All threads wait for the 25.6 KB to land (phase 0).
    {
        uint32_t done;
        asm volatile(
            "{\n\t"
            ".reg .pred p;\n\t"
            "mbarrier.try_wait.parity.acquire.cta.shared::cta.b64 p, [%1], %2;\n\t"
            "selp.b32 %0, 1, 0, p;\n\t"
            "}"
            : "=r"(done) : "r"(mbar_a), "r"(0u) : "memory");
        if (!done) {
            asm volatile(
                "{\n\t"
                ".reg .pred P1;\n\t"
                "WAIT_LOOP_%=:\n\t"
                "mbarrier.try_wait.parity.acquire.cta.shared::cta.b64 P1, [%0], %1, 0x989680;\n\t"
                "@P1 bra.uni WAIT_DONE_%=;\n\t"
                "bra.uni WAIT_LOOP_%=;\n\t"
                "WAIT_DONE_%=:\n\t"
                "}"
                :: "r"(mbar_a), "r"(0u) : "memory");
        }
    }

    // ---- compute: 1 pixel per thread ----
    int p  = pos0 + tid;
    int h  = p / W_;
    int w  = p - h * W_;

    const float* dp = data + (size_t)b * C_ * HW;
    float*       op = out  + (size_t)b * C_ * HW + p;

    float sum = 0.0f, acc0 = 0.0f, acc1 = 0.0f, acc2 = 0.0f;

    bool interior = (h >= R_) & (h < H_ - R_) & (w >= R_) & (w < W_ - R_);

    if (interior) {
        #pragma unroll
        for (int i = 0; i < K_; i++) {
            // taps for this row from smem (conflict-free: stride-1 per warp)
            float e[K_];
            #pragma unroll
            for (int j = 0; j < K_; j++)
                e[j] = __expf(sk[(i * K_ + j) * TPB + tid]);   // shift-free softmax

            const float* drow = dp + (h + i - R_) * W_ + (w - R_);
            float d0[K_], d1[K_], d2[K_];
            #pragma unroll
            for (int j = 0; j < K_; j++) d0[j] = drow[j];
            #pragma unroll
            for (int j = 0; j < K_; j++) d1[j] = drow[j + HW];
            #pragma unroll
            for (int j = 0; j < K_; j++) d2[j] = drow[j + 2 * HW];

            #pragma unroll
            for (int j = 0; j < K_; j++) {
                sum  += e[j];
                acc0 += e[j] * d0[j];
                acc1 += e[j] * d1[j];
                acc2 += e[j] * d2[j];
            }
        }
    } else {
        #pragma unroll
        for (int i = 0; i < K_; i++) {
            int yy = h + i - R_;
            bool yok = (yy >= 0) & (yy < H_);
            #pragma unroll
            for (int j = 0; j < K_; j++) {
                int xx = w + j - R_;
                float e = __expf(sk[(i * K_ + j) * TPB + tid]);
                sum += e;                           // denom includes ALL taps
                if (yok & (xx >= 0) & (xx < W_)) {
                    const float* d0 = dp + yy * W_ + xx;
                    acc0 += e * d0[0];
                    acc1 += e * d0[HW];
                    acc2 += e * d0[2 * HW];
                }
            }
        }
    }

    float inv = __frcp_rn(sum);
    op[0]      = acc0 * inv;
    op[HW]     = acc1 * inv;
    op[2 * HW] = acc2 * inv;
}

extern "C" void kernel_launch(void* const* d_in, const int* in_sizes, int n_in,
                              void* d_out, int out_size)
{
    const float* data = (const float*)d_in[0];
    const float* kern = (const float*)d_in[1];
    float* out = (float*)d_out;

    const int blocks = B_ * H_ * W_ / TPB;       // 14400 tiles
    kpn_apply_v5<<<blocks, TPB>>>(data, kern, out);
}